// round 4
// baseline (speedup 1.0000x reference)
#include <cuda_runtime.h>
#include <cstdint>

#define SEQ 512
#define BATCH 32
#define INP 1024
#define HID 1024
#define G4 4096
#define NLAYERS 4

typedef unsigned long long ull;

// ---------------- scratch (device globals; no cudaMalloc allowed) ----------------
__device__ float g_xg[(size_t)SEQ * BATCH * G4];      // x_gates for current layer
__device__ float g_buf0[(size_t)SEQ * BATCH * HID];   // layer output ping
__device__ float g_buf1[(size_t)SEQ * BATCH * HID];   // layer output pong
__device__ unsigned g_cnt[SEQ];                       // per-timestep arrival counters (self-resetting)

// ---------------- packed fp32 helpers ----------------
__device__ __forceinline__ ull ffma2(ull a, ull b, ull c) {
    ull d;
    asm("fma.rn.f32x2 %0, %1, %2, %3;" : "=l"(d) : "l"(a), "l"(b), "l"(c));
    return d;
}
__device__ __forceinline__ float hsum2(ull a) {
    float2 f;
    asm("mov.b64 {%0, %1}, %2;" : "=f"(f.x), "=f"(f.y) : "l"(a));
    return f.x + f.y;
}
__device__ __forceinline__ void cpasync16(void* dst, const void* src) {
    unsigned s = (unsigned)__cvta_generic_to_shared(dst);
    asm volatile("cp.async.cg.shared.global [%0], [%1], 16;\n" :: "r"(s), "l"(src));
}

// =======================================================================
// Input-projection GEMM: C[m,n] = X[m,:]·W[n,:] + bih[n] + bhh[n]
// X:[16384,1024] W:[4096,1024] -> g_xg[16384,4096]
// 128x128 tile, 256 thr, 8x8 per-thread (strided 16), k-packed FFMA2.
// =======================================================================
#define GAP 20                         // smem pitch (floats): 5*tx mod 32 distinct -> conflict-free
#define GSM_FLOATS (4 * 128 * GAP)     // As[2][128*GAP] + Bs[2][128*GAP]

__global__ __launch_bounds__(256) void gemm_input_kernel(
    const float* __restrict__ Xext, int xsel,
    const float* __restrict__ W,
    const float* __restrict__ bih,
    const float* __restrict__ bhh)
{
    const float* __restrict__ X = (xsel == 0) ? Xext : (xsel == 1 ? g_buf0 : g_buf1);
    extern __shared__ float gs[];
    float* As = gs;                    // [2][128*GAP]
    float* Bs = gs + 2 * 128 * GAP;    // [2][128*GAP]

    const int tid = threadIdx.x;
    const int tx = tid & 15;           // m = mB + tx + 16*i
    const int ty = tid >> 4;           // n = nB + ty + 16*j
    const int mB = blockIdx.y << 7;
    const int nB = blockIdx.x << 7;

    ull acc[8][8];
    #pragma unroll
    for (int i = 0; i < 8; i++)
        #pragma unroll
        for (int j = 0; j < 8; j++) acc[i][j] = 0ull;

    // prologue: stage 0
    for (int u = tid; u < 1024; u += 256) {
        int v = u & 511, row = v >> 2, s4 = (v & 3) << 2;
        if (u < 512)
            cpasync16(&As[row * GAP + s4], &X[(size_t)(mB + row) * INP + s4]);
        else
            cpasync16(&Bs[row * GAP + s4], &W[(size_t)(nB + row) * INP + s4]);
    }
    asm volatile("cp.async.commit_group;\n");

    for (int c = 0; c < 64; c++) {
        if (c < 63) {
            int boff = ((c + 1) & 1) * 128 * GAP;
            int kc = (c + 1) << 4;
            for (int u = tid; u < 1024; u += 256) {
                int v = u & 511, row = v >> 2, s4 = (v & 3) << 2;
                if (u < 512)
                    cpasync16(&As[boff + row * GAP + s4],
                              &X[(size_t)(mB + row) * INP + kc + s4]);
                else
                    cpasync16(&Bs[boff + row * GAP + s4],
                              &W[(size_t)(nB + row) * INP + kc + s4]);
            }
            asm volatile("cp.async.commit_group;\n");
            asm volatile("cp.async.wait_group 1;\n");
        } else {
            asm volatile("cp.async.wait_group 0;\n");
        }
        __syncthreads();

        const float* ab = As + (c & 1) * 128 * GAP;
        const float* bb = Bs + (c & 1) * 128 * GAP;
        #pragma unroll
        for (int q = 0; q < 4; q++) {
            int k = q << 2;
            ulonglong2 av[8], bv[8];
            #pragma unroll
            for (int i = 0; i < 8; i++)
                av[i] = *(const ulonglong2*)&ab[(tx + (i << 4)) * GAP + k];
            #pragma unroll
            for (int j = 0; j < 8; j++)
                bv[j] = *(const ulonglong2*)&bb[(ty + (j << 4)) * GAP + k];
            #pragma unroll
            for (int i = 0; i < 8; i++)
                #pragma unroll
                for (int j = 0; j < 8; j++) {
                    acc[i][j] = ffma2(av[i].x, bv[j].x, acc[i][j]);
                    acc[i][j] = ffma2(av[i].y, bv[j].y, acc[i][j]);
                }
        }
        __syncthreads();
    }

    // epilogue
    float bsum[8];
    #pragma unroll
    for (int j = 0; j < 8; j++) {
        int n = nB + ty + (j << 4);
        bsum[j] = bih[n] + bhh[n];
    }
    #pragma unroll
    for (int i = 0; i < 8; i++) {
        size_t m = (size_t)(mB + tx + (i << 4));
        #pragma unroll
        for (int j = 0; j < 8; j++) {
            int n = nB + ty + (j << 4);
            g_xg[m * G4 + n] = hsum2(acc[i][j]) + bsum[j];
        }
    }
}

// =======================================================================
// Persistent recurrence kernel
// 128 CTAs; CTA cb owns h-cols [cb*8, cb*8+8) => 32 gate rows (r>>3 = gate, r&7 = j)
// 256 thr: ks = tid>>6 (k-split 4), p = tid&63: rq = p&7 (4 rows), bq = p>>3 (4 batches)
// 4x4 per-thread tile, k-packed FFMA2; W resident in smem; h double-buffered 64-k stages.
// =======================================================================
#define WPITCH 1028                      // w rows 16B aligned; groups 4*rq distinct
#define HPITCH 68                        // h rows 16B aligned; groups 4*bq distinct
#define HBLK (32 * HPITCH)               // one (buf, ks) block
#define REC_SMEM_FLOATS (32 * WPITCH + 8 * HBLK + 256 * 16 + 32 * 36 + 256)

__global__ __launch_bounds__(256) void lstm_rec_kernel(
    const float* __restrict__ Whh,    // [4096, 1024] (layer slice)
    int ysel, float* __restrict__ ysext,
    float* __restrict__ hout, float* __restrict__ cout)
{
    float* ys = (ysel == 0) ? g_buf0 : (ysel == 1 ? g_buf1 : ysext);
    extern __shared__ float sm[];
    float* ws  = sm;                      // [32][WPITCH]
    float* hs  = ws + 32 * WPITCH;        // [2][4][32][HPITCH]
    float* red = hs + 8 * HBLK;           // [256][16]
    float* Gs  = red + 256 * 16;          // [32][36]
    float* cs  = Gs + 32 * 36;            // [32][8]

    const int tid = threadIdx.x;
    const int ks = tid >> 6;              // k-range [ks*256, ks*256+256)
    const int p  = tid & 63;
    const int rq = p & 7;                 // rows 4rq..4rq+3
    const int bq = p >> 3;                // batches 4bq..4bq+3
    const int c0 = blockIdx.x << 3;
    const int ab = tid >> 3, aj = tid & 7;   // activation mapping
    const int pp = tid >> 2, jb = (tid & 3) << 2;  // reduction mapping

    // ---- load W slice into smem once: ws[r][k] ----
    for (int u = tid; u < 8192; u += 256) {
        int r = u >> 8, s = (u & 255) << 2;
        int grow = ((r >> 3) << 10) + c0 + (r & 7);
        *(float4*)&ws[r * WPITCH + s] = *(const float4*)&Whh[(size_t)grow * HID + s];
    }
    cs[ab * 8 + aj] = 0.f;
    __syncthreads();

    const float* wr0 = ws + (4 * rq + 0) * WPITCH + (ks << 8);
    const float* wr1 = ws + (4 * rq + 1) * WPITCH + (ks << 8);
    const float* wr2 = ws + (4 * rq + 2) * WPITCH + (ks << 8);
    const float* wr3 = ws + (4 * rq + 3) * WPITCH + (ks << 8);

    for (int t = 0; t < SEQ; t++) {
        // prefetch this step's x_gates early (independent of h)
        const float* xgp = g_xg + ((size_t)t * BATCH + ab) * G4 + c0 + aj;
        float xgi = xgp[0], xgf = xgp[1024], xgg = xgp[2048], xgo = xgp[3072];

        ull acc[4][4];
        #pragma unroll
        for (int i = 0; i < 4; i++)
            #pragma unroll
            for (int j = 0; j < 4; j++) acc[i][j] = 0ull;

        if (t > 0) {
            if (tid == 0) {
                volatile unsigned* fp = &g_cnt[t - 1];
                while (*fp < 128u) { __nanosleep(20); }
                __threadfence();
            }
            __syncthreads();
            const float* hsrc = ys + (size_t)(t - 1) * BATCH * HID;

            // prefetch stage 0: for each ks, k-range [ks*256, ks*256+64)
            for (int u = tid; u < 2048; u += 256) {
                int uks = u >> 9, b = (u >> 4) & 31, s = (u & 15) << 2;
                cpasync16(&hs[(uks * 32 + b) * HPITCH + s],
                          hsrc + (size_t)b * HID + (uks << 8) + s);
            }
            asm volatile("cp.async.commit_group;\n");

            for (int c = 0; c < 4; c++) {
                if (c < 3) {
                    int boff = (((c + 1) & 1) * 4) * HBLK;
                    int koff = ((c + 1) << 6);
                    for (int u = tid; u < 2048; u += 256) {
                        int uks = u >> 9, b = (u >> 4) & 31, s = (u & 15) << 2;
                        cpasync16(&hs[boff + (uks * 32 + b) * HPITCH + s],
                                  hsrc + (size_t)b * HID + (uks << 8) + koff + s);
                    }
                    asm volatile("cp.async.commit_group;\n");
                    asm volatile("cp.async.wait_group 1;\n");
                } else {
                    asm volatile("cp.async.wait_group 0;\n");
                }
                __syncthreads();

                const float* hb = hs + ((c & 1) * 4 + ks) * HBLK + (4 * bq) * HPITCH;
                const float* w0 = wr0 + (c << 6);
                const float* w1 = wr1 + (c << 6);
                const float* w2 = wr2 + (c << 6);
                const float* w3 = wr3 + (c << 6);
                #pragma unroll 8
                for (int q = 0; q < 16; q++) {
                    int k = q << 2;
                    ulonglong2 h0 = *(const ulonglong2*)&hb[k];
                    ulonglong2 h1 = *(const ulonglong2*)&hb[HPITCH + k];
                    ulonglong2 h2 = *(const ulonglong2*)&hb[2 * HPITCH + k];
                    ulonglong2 h3 = *(const ulonglong2*)&hb[3 * HPITCH + k];
                    ulonglong2 v0 = *(const ulonglong2*)&w0[k];
                    ulonglong2 v1 = *(const ulonglong2*)&w1[k];
                    ulonglong2 v2 = *(const ulonglong2*)&w2[k];
                    ulonglong2 v3 = *(const ulonglong2*)&w3[k];
                    acc[0][0] = ffma2(h0.x, v0.x, acc[0][0]); acc[0][0] = ffma2(h0.y, v0.y, acc[0][0]);
                    acc[0][1] = ffma2(h1.x, v0.x, acc[0][1]); acc[0][1] = ffma2(h1.y, v0.y, acc[0][1]);
                    acc[0][2] = ffma2(h2.x, v0.x, acc[0][2]); acc[0][2] = ffma2(h2.y, v0.y, acc[0][2]);
                    acc[0][3] = ffma2(h3.x, v0.x, acc[0][3]); acc[0][3] = ffma2(h3.y, v0.y, acc[0][3]);
                    acc[1][0] = ffma2(h0.x, v1.x, acc[1][0]); acc[1][0] = ffma2(h0.y, v1.y, acc[1][0]);
                    acc[1][1] = ffma2(h1.x, v1.x, acc[1][1]); acc[1][1] = ffma2(h1.y, v1.y, acc[1][1]);
                    acc[1][2] = ffma2(h2.x, v1.x, acc[1][2]); acc[1][2] = ffma2(h2.y, v1.y, acc[1][2]);
                    acc[1][3] = ffma2(h3.x, v1.x, acc[1][3]); acc[1][3] = ffma2(h3.y, v1.y, acc[1][3]);
                    acc[2][0] = ffma2(h0.x, v2.x, acc[2][0]); acc[2][0] = ffma2(h0.y, v2.y, acc[2][0]);
                    acc[2][1] = ffma2(h1.x, v2.x, acc[2][1]); acc[2][1] = ffma2(h1.y, v2.y, acc[2][1]);
                    acc[2][2] = ffma2(h2.x, v2.x, acc[2][2]); acc[2][2] = ffma2(h2.y, v2.y, acc[2][2]);
                    acc[2][3] = ffma2(h3.x, v2.x, acc[2][3]); acc[2][3] = ffma2(h3.y, v2.y, acc[2][3]);
                    acc[3][0] = ffma2(h0.x, v3.x, acc[3][0]); acc[3][0] = ffma2(h0.y, v3.y, acc[3][0]);
                    acc[3][1] = ffma2(h1.x, v3.x, acc[3][1]); acc[3][1] = ffma2(h1.y, v3.y, acc[3][1]);
                    acc[3][2] = ffma2(h2.x, v3.x, acc[3][2]); acc[3][2] = ffma2(h2.y, v3.y, acc[3][2]);
                    acc[3][3] = ffma2(h3.x, v3.x, acc[3][3]); acc[3][3] = ffma2(h3.y, v3.y, acc[3][3]);
                }
                __syncthreads();
            }
        } else {
            __syncthreads();
        }

        // ---- partial sums -> red[tid][16] ----
        {
            float r4[16];
            #pragma unroll
            for (int i = 0; i < 4; i++)
                #pragma unroll
                for (int j = 0; j < 4; j++)
                    r4[i * 4 + j] = hsum2(acc[i][j]);
            #pragma unroll
            for (int v = 0; v < 4; v++)
                *(float4*)&red[tid * 16 + v * 4] = *(float4*)&r4[v * 4];
        }
        __syncthreads();

        // ---- k-split reduction: 4 partials -> Gs[r][b] ----
        {
            float4 s0 = *(const float4*)&red[(0 * 64 + pp) * 16 + jb];
            float4 s1 = *(const float4*)&red[(1 * 64 + pp) * 16 + jb];
            float4 s2 = *(const float4*)&red[(2 * 64 + pp) * 16 + jb];
            float4 s3 = *(const float4*)&red[(3 * 64 + pp) * 16 + jb];
            float4 s;
            s.x = (s0.x + s1.x) + (s2.x + s3.x);
            s.y = (s0.y + s1.y) + (s2.y + s3.y);
            s.z = (s0.z + s1.z) + (s2.z + s3.z);
            s.w = (s0.w + s1.w) + (s2.w + s3.w);
            int r = ((pp & 7) << 2) + (tid & 3);
            int b0 = (pp >> 3) << 2;
            *(float4*)&Gs[r * 36 + b0] = s;
        }
        __syncthreads();

        // ---- activation ----
        {
            float gi = Gs[aj * 36 + ab]        + xgi;
            float gf = Gs[(8 + aj) * 36 + ab]  + xgf;
            float gg = Gs[(16 + aj) * 36 + ab] + xgg;
            float go = Gs[(24 + aj) * 36 + ab] + xgo;
            float si = 1.f / (1.f + expf(-gi));
            float sf = 1.f / (1.f + expf(-gf));
            float so = 1.f / (1.f + expf(-go));
            float tg = tanhf(gg);
            float cv = sf * cs[ab * 8 + aj] + si * tg;
            float hv = so * tanhf(cv);
            cs[ab * 8 + aj] = cv;
            ys[((size_t)t * BATCH + ab) * HID + c0 + aj] = hv;
            if (t == SEQ - 1) {
                hout[ab * HID + c0 + aj] = hv;
                cout[ab * HID + c0 + aj] = cv;
            }
        }
        __syncthreads();
        if (tid == 0) {
            __threadfence();
            unsigned old = atomicAdd(&g_cnt[t], 1u);
            if (t == SEQ - 1 && old == 127u) {
                for (int i = 0; i < SEQ; i++) g_cnt[i] = 0u;
            }
        }
    }
}

// ---------------- host launcher ----------------
extern "C" void kernel_launch(void* const* d_in, const int* in_sizes, int n_in,
                              void* d_out, int out_size) {
    const float* x   = (const float*)d_in[0];
    const float* Wih = (const float*)d_in[1];
    const float* Whh = (const float*)d_in[2];
    const float* bih = (const float*)d_in[3];
    const float* bhh = (const float*)d_in[4];
    float* out   = (float*)d_out;
    float* hbase = out + (size_t)SEQ * BATCH * HID;         // [L,B,H]
    float* cbase = hbase + (size_t)NLAYERS * BATCH * HID;   // [L,B,H]

    const int rec_smem  = REC_SMEM_FLOATS * 4;
    const int gemm_smem = GSM_FLOATS * 4;
    cudaFuncSetAttribute(lstm_rec_kernel,
                         cudaFuncAttributeMaxDynamicSharedMemorySize, rec_smem);

    dim3 ggrid(G4 / 128, (SEQ * BATCH) / 128);
    for (int l = 0; l < NLAYERS; l++) {
        // layer IO ping-pong: l0:x->buf0, l1:buf0->buf1, l2:buf1->buf0, l3:buf0->d_out
        int xsel = (l == 0) ? 0 : ((l == 1) ? 1 : ((l == 2) ? 2 : 1));
        int ysel = (l == 0) ? 0 : ((l == 1) ? 1 : ((l == 2) ? 0 : 2));
        gemm_input_kernel<<<ggrid, 256, gemm_smem>>>(x, xsel,
            Wih + (size_t)l * G4 * INP,
            bih + (size_t)l * G4,
            bhh + (size_t)l * G4);
        lstm_rec_kernel<<<128, 256, rec_smem>>>(Whh + (size_t)l * G4 * HID, ysel, out,
            hbase + (size_t)l * BATCH * HID,
            cbase + (size_t)l * BATCH * HID);
    }
}

// round 5
// speedup vs baseline: 1.1448x; 1.1448x over previous
#include <cuda_runtime.h>
#include <cstdint>

#define SEQ 512
#define BATCH 32
#define INP 1024
#define HID 1024
#define G4 4096
#define NLAYERS 4

typedef unsigned long long ull;

// ---------------- scratch (device globals; no cudaMalloc allowed) ----------------
__device__ float g_xg[(size_t)SEQ * BATCH * G4];      // x_gates for current layer
__device__ float g_buf0[(size_t)SEQ * BATCH * HID];   // layer output ping
__device__ float g_buf1[(size_t)SEQ * BATCH * HID];   // layer output pong
__device__ int   g_slot[128];                         // per-CTA progress slots (reset by GEMM)

// ---------------- packed fp32 helpers ----------------
__device__ __forceinline__ ull ffma2(ull a, ull b, ull c) {
    ull d;
    asm("fma.rn.f32x2 %0, %1, %2, %3;" : "=l"(d) : "l"(a), "l"(b), "l"(c));
    return d;
}
__device__ __forceinline__ float hsum2(ull a) {
    float2 f;
    asm("mov.b64 {%0, %1}, %2;" : "=f"(f.x), "=f"(f.y) : "l"(a));
    return f.x + f.y;
}
__device__ __forceinline__ void cpasync8(void* dst, const void* src) {
    unsigned s = (unsigned)__cvta_generic_to_shared(dst);
    asm volatile("cp.async.ca.shared.global [%0], [%1], 8;\n" :: "r"(s), "l"(src));
}

// ---------------- input-projection GEMM (R3-proven) ----------------
// C[m,n] = X[m,:]·W[n,:] + bih[n] + bhh[n];  X:[16384,1024], W:[4096,1024] -> g_xg
#define GP 34   // smem pitch (floats): bank = (2*row + k) % 32 -> conflict-free
__global__ __launch_bounds__(256) void gemm_input_kernel(
    const float* __restrict__ Xext, int xsel,
    const float* __restrict__ W,
    const float* __restrict__ bih,
    const float* __restrict__ bhh)
{
    // reset recurrence progress slots for the upcoming rec launch (stream-ordered)
    if (blockIdx.x == 0 && blockIdx.y == 0 && threadIdx.x < 128)
        g_slot[threadIdx.x] = 0;

    const float* __restrict__ X = (xsel == 0) ? Xext : (xsel == 1 ? g_buf0 : g_buf1);
    __shared__ float As[64 * GP];
    __shared__ float Bs[64 * GP];
    const int tid = threadIdx.x;
    const int tx = tid & 15, ty = tid >> 4;
    const int mB = blockIdx.y << 6;
    const int nB = blockIdx.x << 6;

    ull acc[4][4];
    #pragma unroll
    for (int i = 0; i < 4; i++)
        #pragma unroll
        for (int j = 0; j < 4; j++) acc[i][j] = 0ull;

    for (int kc = 0; kc < INP; kc += 32) {
        for (int u = tid; u < 512; u += 256) {
            int row = u >> 3, seg = (u & 7) << 2;
            float4 v = *(const float4*)&X[(size_t)(mB + row) * INP + kc + seg];
            float* p = As + row * GP + seg;
            p[0] = v.x; p[1] = v.y; p[2] = v.z; p[3] = v.w;
            float4 w = *(const float4*)&W[(size_t)(nB + row) * INP + kc + seg];
            float* q = Bs + row * GP + seg;
            q[0] = w.x; q[1] = w.y; q[2] = w.z; q[3] = w.w;
        }
        __syncthreads();
        #pragma unroll
        for (int kp = 0; kp < 16; kp++) {
            ull a[4], b[4];
            #pragma unroll
            for (int i = 0; i < 4; i++)
                a[i] = *(const ull*)&As[(ty + 16 * i) * GP + 2 * kp];
            #pragma unroll
            for (int j = 0; j < 4; j++)
                b[j] = *(const ull*)&Bs[(tx + 16 * j) * GP + 2 * kp];
            #pragma unroll
            for (int i = 0; i < 4; i++)
                #pragma unroll
                for (int j = 0; j < 4; j++)
                    acc[i][j] = ffma2(a[i], b[j], acc[i][j]);
        }
        __syncthreads();
    }

    float bsum[4];
    #pragma unroll
    for (int j = 0; j < 4; j++) {
        int n = nB + tx + 16 * j;
        bsum[j] = bih[n] + bhh[n];
    }
    #pragma unroll
    for (int i = 0; i < 4; i++) {
        size_t m = (size_t)(mB + ty + 16 * i);
        #pragma unroll
        for (int j = 0; j < 4; j++) {
            int n = nB + tx + 16 * j;
            g_xg[m * G4 + n] = hsum2(acc[i][j]) + bsum[j];
        }
    }
}

// ---------------- persistent recurrence kernel ----------------
// 128 CTAs; CTA cb owns h-columns [cb*8, cb*8+8) => 32 gate rows {g*1024 + cb*8 + j}.
// W_hh slice (32x1024 f32) resident in smem; h double-buffered in 256-k chunks.
#define WP 1028     // weight pitch (floats): 16B-aligned rows; conflict-free LDS.128
#define HP 258      // h pitch (floats): bank = (2*tx + k) % 32 -> conflict-free LDS.64
#define REC_SMEM_FLOATS (32 * WP + 2 * 32 * HP + 32 * 33 + 32 * 8)

__global__ __launch_bounds__(256) void lstm_rec_kernel(
    const float* __restrict__ Whh,    // [4096, 1024] (layer slice)
    int ysel, float* __restrict__ ysext,
    float* __restrict__ hout, float* __restrict__ cout)
{
    float* ys = (ysel == 0) ? g_buf0 : (ysel == 1 ? g_buf1 : ysext);
    extern __shared__ float sm[];
    float* ws = sm;                       // [32][WP]
    float* hs = ws + 32 * WP;             // [2][32][HP]
    float* Gs = hs + 2 * 32 * HP;         // [32][33]
    float* cs = Gs + 32 * 33;             // [32][8]

    const int tid = threadIdx.x;
    const int tx = tid & 15;              // batch base: b = tx, tx+16
    const int ty = tid >> 4;              // row base:   r = ty, ty+16
    const int c0 = blockIdx.x << 3;
    const int ab = tid >> 3, aj = tid & 7;   // activation mapping

    // ---- load W slice into smem once ----
    for (int u = tid; u < 8192; u += 256) {
        int r = u >> 8, s = (u & 255) << 2;
        int grow = ((r >> 3) << 10) + c0 + (r & 7);
        *(float4*)&ws[r * WP + s] = *(const float4*)&Whh[(size_t)grow * HID + s];
    }
    cs[ab * 8 + aj] = 0.f;
    __syncthreads();

    const float* wr0 = ws + ty * WP;
    const float* wr1 = ws + (ty + 16) * WP;

    for (int t = 0; t < SEQ; t++) {
        // prefetch this step's x_gates early (independent of h)
        const float* xgp = g_xg + ((size_t)t * BATCH + ab) * G4 + c0 + aj;
        float xgi = xgp[0], xgf = xgp[1024], xgg = xgp[2048], xgo = xgp[3072];

        ull a00a = 0, a00b = 0, a01a = 0, a01b = 0;
        ull a10a = 0, a10b = 0, a11a = 0, a11b = 0;

        if (t > 0) {
            // ---- parallel flag wait: thread i polls CTA i's slot ----
            for (;;) {
                int ok = 1;
                if (tid < 128) {
                    int v;
                    asm volatile("ld.acquire.gpu.global.b32 %0, [%1];"
                                 : "=r"(v) : "l"(g_slot + tid) : "memory");
                    ok = (v >= t);
                }
                if (__syncthreads_and(ok)) break;
            }
            const float* hsrc = ys + (size_t)(t - 1) * BATCH * HID;

            // prefetch chunk 0 (k = 0..255)
            for (int u = tid; u < 4096; u += 256) {
                int row = u >> 7, s2 = (u & 127) << 1;
                cpasync8(&hs[row * HP + s2], hsrc + (size_t)row * HID + s2);
            }
            asm volatile("cp.async.commit_group;\n");

            for (int kc = 0; kc < 4; kc++) {
                asm volatile("cp.async.wait_group 0;\n");
                __syncthreads();          // chunk kc ready for all; all finished kc-1
                if (kc < 3) {             // prefetch kc+1 (overwrites buffer of kc-1: safe)
                    int buf = (kc + 1) & 1;
                    const float* src = hsrc + ((kc + 1) << 8);
                    float* dst = hs + buf * 32 * HP;
                    for (int u = tid; u < 4096; u += 256) {
                        int row = u >> 7, s2 = (u & 127) << 1;
                        cpasync8(dst + row * HP + s2, src + (size_t)row * HID + s2);
                    }
                    asm volatile("cp.async.commit_group;\n");
                }

                const float* hb0 = hs + (kc & 1) * 32 * HP + tx * HP;
                const float* hb1 = hs + (kc & 1) * 32 * HP + (tx + 16) * HP;
                const float* w0p = wr0 + (kc << 8);
                const float* w1p = wr1 + (kc << 8);
                #pragma unroll 8
                for (int q = 0; q < 64; q++) {
                    int k = q << 2;
                    ull h00 = *(const ull*)(hb0 + k);
                    ull h02 = *(const ull*)(hb0 + k + 2);
                    ull h10 = *(const ull*)(hb1 + k);
                    ull h12 = *(const ull*)(hb1 + k + 2);
                    ulonglong2 w0 = *(const ulonglong2*)(w0p + k);
                    ulonglong2 w1 = *(const ulonglong2*)(w1p + k);
                    a00a = ffma2(h00, w0.x, a00a);
                    a00b = ffma2(h02, w0.y, a00b);
                    a01a = ffma2(h00, w1.x, a01a);
                    a01b = ffma2(h02, w1.y, a01b);
                    a10a = ffma2(h10, w0.x, a10a);
                    a10b = ffma2(h12, w0.y, a10b);
                    a11a = ffma2(h10, w1.x, a11a);
                    a11b = ffma2(h12, w1.y, a11b);
                }
            }
            __syncthreads();              // protect hs before Gs phase reuses nothing; order accs done
        } else {
            __syncthreads();
        }

        // stage gate preactivations: Gs[local_row][batch]
        Gs[ty * 33 + tx]             = hsum2(a00a) + hsum2(a00b);
        Gs[ty * 33 + tx + 16]        = hsum2(a10a) + hsum2(a10b);
        Gs[(ty + 16) * 33 + tx]      = hsum2(a01a) + hsum2(a01b);
        Gs[(ty + 16) * 33 + tx + 16] = hsum2(a11a) + hsum2(a11b);
        __syncthreads();

        {
            float gi = Gs[aj * 33 + ab]        + xgi;
            float gf = Gs[(8 + aj) * 33 + ab]  + xgf;
            float gg = Gs[(16 + aj) * 33 + ab] + xgg;
            float go = Gs[(24 + aj) * 33 + ab] + xgo;
            float si = 1.f / (1.f + expf(-gi));
            float sf = 1.f / (1.f + expf(-gf));
            float so = 1.f / (1.f + expf(-go));
            float tg = tanhf(gg);
            float cv = sf * cs[ab * 8 + aj] + si * tg;
            float hv = so * tanhf(cv);
            cs[ab * 8 + aj] = cv;
            ys[((size_t)t * BATCH + ab) * HID + c0 + aj] = hv;
            if (t == SEQ - 1) {
                hout[ab * HID + c0 + aj] = hv;
                cout[ab * HID + c0 + aj] = cv;
            }
        }
        __syncthreads();                  // all ys stores done
        if (tid == 0) {
            __threadfence();
            asm volatile("st.release.gpu.global.b32 [%0], %1;"
                         :: "l"(g_slot + blockIdx.x), "r"(t + 1) : "memory");
        }
    }
}

// ---------------- host launcher ----------------
extern "C" void kernel_launch(void* const* d_in, const int* in_sizes, int n_in,
                              void* d_out, int out_size) {
    const float* x   = (const float*)d_in[0];
    const float* Wih = (const float*)d_in[1];
    const float* Whh = (const float*)d_in[2];
    const float* bih = (const float*)d_in[3];
    const float* bhh = (const float*)d_in[4];
    float* out   = (float*)d_out;
    float* hbase = out + (size_t)SEQ * BATCH * HID;         // [L,B,H]
    float* cbase = hbase + (size_t)NLAYERS * BATCH * HID;   // [L,B,H]

    const int rec_smem = REC_SMEM_FLOATS * 4;
    cudaFuncSetAttribute(lstm_rec_kernel,
                         cudaFuncAttributeMaxDynamicSharedMemorySize, rec_smem);

    dim3 ggrid(G4 / 64, (SEQ * BATCH) / 64);
    for (int l = 0; l < NLAYERS; l++) {
        // layer IO ping-pong: l0:x->buf0, l1:buf0->buf1, l2:buf1->buf0, l3:buf0->d_out
        int xsel = (l == 0) ? 0 : ((l == 1) ? 1 : ((l == 2) ? 2 : 1));
        int ysel = (l == 0) ? 0 : ((l == 1) ? 1 : ((l == 2) ? 0 : 2));
        gemm_input_kernel<<<ggrid, 256>>>(x, xsel,
            Wih + (size_t)l * G4 * INP,
            bih + (size_t)l * G4,
            bhh + (size_t)l * G4);
        lstm_rec_kernel<<<128, 256, rec_smem>>>(Whh + (size_t)l * G4 * HID, ysel, out,
            hbase + (size_t)l * BATCH * HID,
            cbase + (size_t)l * BATCH * HID);
    }
}

// round 6
// speedup vs baseline: 1.2039x; 1.0516x over previous
#include <cuda_runtime.h>
#include <cstdint>

#define SEQ 512
#define BATCH 32
#define INP 1024
#define HID 1024
#define G4 4096
#define NLAYERS 4

typedef unsigned long long ull;

// ---------------- scratch (device globals; no cudaMalloc allowed) ----------------
__device__ float g_xg[(size_t)SEQ * BATCH * G4];      // x_gates for current layer
__device__ float g_buf0[(size_t)SEQ * BATCH * HID];   // layer output ping
__device__ float g_buf1[(size_t)SEQ * BATCH * HID];   // layer output pong
__device__ int   g_gcnt[4];                           // per-group progress counters (reset by GEMM)

// ---------------- packed fp32 helpers ----------------
__device__ __forceinline__ ull ffma2(ull a, ull b, ull c) {
    ull d;
    asm("fma.rn.f32x2 %0, %1, %2, %3;" : "=l"(d) : "l"(a), "l"(b), "l"(c));
    return d;
}
__device__ __forceinline__ float hsum2(ull a) {
    float2 f;
    asm("mov.b64 {%0, %1}, %2;" : "=f"(f.x), "=f"(f.y) : "l"(a));
    return f.x + f.y;
}
__device__ __forceinline__ void cpasync8(void* dst, const void* src) {
    unsigned s = (unsigned)__cvta_generic_to_shared(dst);
    asm volatile("cp.async.ca.shared.global [%0], [%1], 8;\n" :: "r"(s), "l"(src));
}

// ---------------- input-projection GEMM (R3-proven) ----------------
// C[m,n] = X[m,:]·W[n,:] + bih[n] + bhh[n];  X:[16384,1024], W:[4096,1024] -> g_xg
#define GP 34   // smem pitch (floats): bank = (2*row + k) % 32 -> conflict-free
__global__ __launch_bounds__(256) void gemm_input_kernel(
    const float* __restrict__ Xext, int xsel,
    const float* __restrict__ W,
    const float* __restrict__ bih,
    const float* __restrict__ bhh)
{
    // reset recurrence progress counters for the upcoming rec launch (stream-ordered)
    if (blockIdx.x == 0 && blockIdx.y == 0 && threadIdx.x < 4)
        g_gcnt[threadIdx.x] = 0;

    const float* __restrict__ X = (xsel == 0) ? Xext : (xsel == 1 ? g_buf0 : g_buf1);
    __shared__ float As[64 * GP];
    __shared__ float Bs[64 * GP];
    const int tid = threadIdx.x;
    const int tx = tid & 15, ty = tid >> 4;
    const int mB = blockIdx.y << 6;
    const int nB = blockIdx.x << 6;

    ull acc[4][4];
    #pragma unroll
    for (int i = 0; i < 4; i++)
        #pragma unroll
        for (int j = 0; j < 4; j++) acc[i][j] = 0ull;

    for (int kc = 0; kc < INP; kc += 32) {
        for (int u = tid; u < 512; u += 256) {
            int row = u >> 3, seg = (u & 7) << 2;
            float4 v = *(const float4*)&X[(size_t)(mB + row) * INP + kc + seg];
            float* p = As + row * GP + seg;
            p[0] = v.x; p[1] = v.y; p[2] = v.z; p[3] = v.w;
            float4 w = *(const float4*)&W[(size_t)(nB + row) * INP + kc + seg];
            float* q = Bs + row * GP + seg;
            q[0] = w.x; q[1] = w.y; q[2] = w.z; q[3] = w.w;
        }
        __syncthreads();
        #pragma unroll
        for (int kp = 0; kp < 16; kp++) {
            ull a[4], b[4];
            #pragma unroll
            for (int i = 0; i < 4; i++)
                a[i] = *(const ull*)&As[(ty + 16 * i) * GP + 2 * kp];
            #pragma unroll
            for (int j = 0; j < 4; j++)
                b[j] = *(const ull*)&Bs[(tx + 16 * j) * GP + 2 * kp];
            #pragma unroll
            for (int i = 0; i < 4; i++)
                #pragma unroll
                for (int j = 0; j < 4; j++)
                    acc[i][j] = ffma2(a[i], b[j], acc[i][j]);
        }
        __syncthreads();
    }

    float bsum[4];
    #pragma unroll
    for (int j = 0; j < 4; j++) {
        int n = nB + tx + 16 * j;
        bsum[j] = bih[n] + bhh[n];
    }
    #pragma unroll
    for (int i = 0; i < 4; i++) {
        size_t m = (size_t)(mB + ty + 16 * i);
        #pragma unroll
        for (int j = 0; j < 4; j++) {
            int n = nB + tx + 16 * j;
            g_xg[m * G4 + n] = hsum2(acc[i][j]) + bsum[j];
        }
    }
}

// ---------------- persistent recurrence kernel ----------------
// 128 CTAs; CTA cb owns h-columns [cb*8, cb*8+8) => 32 gate rows {g*1024 + cb*8 + j}.
// W_hh slice resident in smem; h consumed in 4 chunks of 256 k, chunk g produced by
// CTA group g (CTAs 32g..32g+31). Per-chunk group counters + staggered chunk order.
#define WP 1028     // weight pitch (floats): 16B-aligned rows; conflict-free LDS.128
#define HP 258      // h pitch (floats): bank = (2*tx + k) % 32 -> conflict-free LDS.64
#define REC_SMEM_FLOATS (32 * WP + 2 * 32 * HP + 32 * 33 + 32 * 8)

__global__ __launch_bounds__(256) void lstm_rec_kernel(
    const float* __restrict__ Whh,    // [4096, 1024] (layer slice)
    int ysel, float* __restrict__ ysext,
    float* __restrict__ hout, float* __restrict__ cout)
{
    float* ys = (ysel == 0) ? g_buf0 : (ysel == 1 ? g_buf1 : ysext);
    extern __shared__ float sm[];
    float* ws = sm;                       // [32][WP]
    float* hs = ws + 32 * WP;             // [2][32][HP]
    float* Gs = hs + 2 * 32 * HP;         // [32][33]
    float* cs = Gs + 32 * 33;             // [32][8]

    const int tid = threadIdx.x;
    const int tx = tid & 15;              // batch base: b = tx, tx+16
    const int ty = tid >> 4;              // row base:   r = ty, ty+16
    const int c0 = blockIdx.x << 3;
    const int g0 = blockIdx.x >> 5;       // my producer group (and first chunk)
    const int ab = tid >> 3, aj = tid & 7;   // activation mapping

    // ---- load W slice into smem once ----
    for (int u = tid; u < 8192; u += 256) {
        int r = u >> 8, s = (u & 255) << 2;
        int grow = ((r >> 3) << 10) + c0 + (r & 7);
        *(float4*)&ws[r * WP + s] = *(const float4*)&Whh[(size_t)grow * HID + s];
    }
    cs[ab * 8 + aj] = 0.f;
    __syncthreads();

    const float* wr0 = ws + ty * WP;
    const float* wr1 = ws + (ty + 16) * WP;

    for (int t = 0; t < SEQ; t++) {
        // prefetch this step's x_gates early (independent of h)
        const float* xgp = g_xg + ((size_t)t * BATCH + ab) * G4 + c0 + aj;
        float xgi = xgp[0], xgf = xgp[1024], xgg = xgp[2048], xgo = xgp[3072];

        ull a00a = 0, a00b = 0, a01a = 0, a01b = 0;
        ull a10a = 0, a10b = 0, a11a = 0, a11b = 0;

        if (t > 0) {
            const float* hsrc = ys + (size_t)(t - 1) * BATCH * HID;
            const int need = 32 * t;

            // ---- prologue: wait for own group's chunk, prefetch into buf0 ----
            if (tid == 0) {
                volatile int* p = g_gcnt + g0;
                while (*p < need) {}
                __threadfence();
            }
            __syncthreads();
            for (int u = tid; u < 4096; u += 256) {
                int row = u >> 7, s2 = (u & 127) << 1;
                cpasync8(&hs[row * HP + s2],
                         hsrc + (size_t)row * HID + (g0 << 8) + s2);
            }
            asm volatile("cp.async.commit_group;\n");

            for (int i = 0; i < 4; i++) {
                const int gc = (g0 + i) & 3;
                if (i < 3) {
                    const int gn = (g0 + i + 1) & 3;
                    if (tid == 0) {
                        volatile int* p = g_gcnt + gn;
                        while (*p < need) {}
                        __threadfence();
                    }
                    __syncthreads();   // all may issue cp.async for gn; also proves compute(i-1) done
                    float* dst = hs + ((i + 1) & 1) * 32 * HP;
                    for (int u = tid; u < 4096; u += 256) {
                        int row = u >> 7, s2 = (u & 127) << 1;
                        cpasync8(dst + row * HP + s2,
                                 hsrc + (size_t)row * HID + (gn << 8) + s2);
                    }
                    asm volatile("cp.async.commit_group;\n");
                    asm volatile("cp.async.wait_group 1;\n");
                } else {
                    asm volatile("cp.async.wait_group 0;\n");
                }
                __syncthreads();       // chunk i visible to all warps

                const float* hb0 = hs + (i & 1) * 32 * HP + tx * HP;
                const float* hb1 = hs + (i & 1) * 32 * HP + (tx + 16) * HP;
                const float* w0p = wr0 + (gc << 8);
                const float* w1p = wr1 + (gc << 8);
                #pragma unroll 8
                for (int q = 0; q < 64; q++) {
                    int k = q << 2;
                    ull h00 = *(const ull*)(hb0 + k);
                    ull h02 = *(const ull*)(hb0 + k + 2);
                    ull h10 = *(const ull*)(hb1 + k);
                    ull h12 = *(const ull*)(hb1 + k + 2);
                    ulonglong2 w0 = *(const ulonglong2*)(w0p + k);
                    ulonglong2 w1 = *(const ulonglong2*)(w1p + k);
                    a00a = ffma2(h00, w0.x, a00a);
                    a00b = ffma2(h02, w0.y, a00b);
                    a01a = ffma2(h00, w1.x, a01a);
                    a01b = ffma2(h02, w1.y, a01b);
                    a10a = ffma2(h10, w0.x, a10a);
                    a10b = ffma2(h12, w0.y, a10b);
                    a11a = ffma2(h10, w1.x, a11a);
                    a11b = ffma2(h12, w1.y, a11b);
                }
            }
            __syncthreads();           // all warps done with hs before next phase
        } else {
            __syncthreads();
        }

        // stage gate preactivations: Gs[local_row][batch]
        Gs[ty * 33 + tx]             = hsum2(a00a) + hsum2(a00b);
        Gs[ty * 33 + tx + 16]        = hsum2(a10a) + hsum2(a10b);
        Gs[(ty + 16) * 33 + tx]      = hsum2(a01a) + hsum2(a01b);
        Gs[(ty + 16) * 33 + tx + 16] = hsum2(a11a) + hsum2(a11b);
        __syncthreads();

        {
            float gi = Gs[aj * 33 + ab]        + xgi;
            float gf = Gs[(8 + aj) * 33 + ab]  + xgf;
            float gg = Gs[(16 + aj) * 33 + ab] + xgg;
            float go = Gs[(24 + aj) * 33 + ab] + xgo;
            float si = 1.f / (1.f + expf(-gi));
            float sf = 1.f / (1.f + expf(-gf));
            float so = 1.f / (1.f + expf(-go));
            float tg = tanhf(gg);
            float cv = sf * cs[ab * 8 + aj] + si * tg;
            float hv = so * tanhf(cv);
            cs[ab * 8 + aj] = cv;
            ys[((size_t)t * BATCH + ab) * HID + c0 + aj] = hv;
            if (t == SEQ - 1) {
                hout[ab * HID + c0 + aj] = hv;
                cout[ab * HID + c0 + aj] = cv;
            }
        }
        __syncthreads();               // all ys stores done
        if (tid == 0) {
            __threadfence();
            atomicAdd(&g_gcnt[g0], 1);
        }
    }
}

// ---------------- host launcher ----------------
extern "C" void kernel_launch(void* const* d_in, const int* in_sizes, int n_in,
                              void* d_out, int out_size) {
    const float* x   = (const float*)d_in[0];
    const float* Wih = (const float*)d_in[1];
    const float* Whh = (const float*)d_in[2];
    const float* bih = (const float*)d_in[3];
    const float* bhh = (const float*)d_in[4];
    float* out   = (float*)d_out;
    float* hbase = out + (size_t)SEQ * BATCH * HID;         // [L,B,H]
    float* cbase = hbase + (size_t)NLAYERS * BATCH * HID;   // [L,B,H]

    const int rec_smem = REC_SMEM_FLOATS * 4;
    cudaFuncSetAttribute(lstm_rec_kernel,
                         cudaFuncAttributeMaxDynamicSharedMemorySize, rec_smem);

    dim3 ggrid(G4 / 64, (SEQ * BATCH) / 64);
    for (int l = 0; l < NLAYERS; l++) {
        // layer IO ping-pong: l0:x->buf0, l1:buf0->buf1, l2:buf1->buf0, l3:buf0->d_out
        int xsel = (l == 0) ? 0 : ((l == 1) ? 1 : ((l == 2) ? 2 : 1));
        int ysel = (l == 0) ? 0 : ((l == 1) ? 1 : ((l == 2) ? 0 : 2));
        gemm_input_kernel<<<ggrid, 256>>>(x, xsel,
            Wih + (size_t)l * G4 * INP,
            bih + (size_t)l * G4,
            bhh + (size_t)l * G4);
        lstm_rec_kernel<<<128, 256, rec_smem>>>(Whh + (size_t)l * G4 * HID, ysel, out,
            hbase + (size_t)l * BATCH * HID,
            cbase + (size_t)l * BATCH * HID);
    }
}